// round 6
// baseline (speedup 1.0000x reference)
#include <cuda_runtime.h>

// ---------------- problem constants ----------------
#define NODE_F 192
#define EDGE_F 64
#define DD     256          // inner dim
#define OUTF   2048
#define N_MAX  50000
#define M_MAX  800000

// ---------------- device scratch (no allocs allowed) ----------------
__device__ float g_attr[(size_t)N_MAX * DD];   // 51.2 MB
__device__ float g_v   [(size_t)N_MAX * DD];   // 51.2 MB
__device__ float g_eagg[(size_t)N_MAX * EDGE_F]; // 12.8 MB

// ---------------- f32x2 helpers (FFMA2) ----------------
__device__ __forceinline__ unsigned long long fma2(unsigned long long a,
                                                   unsigned long long b,
                                                   unsigned long long c) {
    unsigned long long d;
    asm("fma.rn.f32x2 %0, %1, %2, %3;" : "=l"(d) : "l"(a), "l"(b), "l"(c));
    return d;
}
__device__ __forceinline__ float2 u2f(unsigned long long u) {
    float2 f;
    asm("mov.b64 {%0, %1}, %2;" : "=f"(f.x), "=f"(f.y) : "l"(u));
    return f;
}

// ---------------- misc kernels ----------------
__global__ void k_zero(float* __restrict__ out, int n) {
    int idx = blockIdx.x * blockDim.x + threadIdx.x;
    if (idx < OUTF) out[idx] = 0.f;
    if (idx < n * EDGE_F) g_eagg[idx] = 0.f;
}

// attr = [node_attr | zeros], float4 granularity (192 % 4 == 0)
__global__ void k_init_attr(const float* __restrict__ node, int n) {
    int idx = blockIdx.x * blockDim.x + threadIdx.x;
    if (idx >= n * (DD / 4)) return;
    int i = idx >> 6;        // node
    int q = idx & 63;        // float4 chunk within row
    float4 v;
    if (q * 4 < NODE_F) v = *(const float4*)&node[(size_t)i * NODE_F + q * 4];
    else                v = make_float4(0.f, 0.f, 0.f, 0.f);
    *(float4*)&g_attr[(size_t)i * DD + q * 4] = v;
}

// precompute once per launch: g_eagg[dst] += edge_attr[e]  (the attr-independent part)
__global__ void k_scatter_edge(const float* __restrict__ eattr,
                               const int* __restrict__ dst, int m) {
    int idx = blockIdx.x * blockDim.x + threadIdx.x;
    if (idx >= m * (EDGE_F / 4)) return;
    int e = idx >> 4;
    int q = idx & 15;
    float4 a = *(const float4*)&eattr[(size_t)e * EDGE_F + q * 4];
    int d2 = __ldg(&dst[e]);
    float* p = &g_eagg[(size_t)d2 * EDGE_F + q * 4];
    atomicAdd(p + 0, a.x); atomicAdd(p + 1, a.y);
    atomicAdd(p + 2, a.z); atomicAdd(p + 3, a.w);
}

// v = attr (+ eagg on last 64 features)
__global__ void k_vinit(int n) {
    int idx = blockIdx.x * blockDim.x + threadIdx.x;
    if (idx >= n * (DD / 4)) return;
    int i = idx >> 6;
    int q = idx & 63;
    float4 a = *(const float4*)&g_attr[(size_t)i * DD + q * 4];
    if (q >= NODE_F / 4) {
        float4 e = *(const float4*)&g_eagg[(size_t)i * EDGE_F + (q - NODE_F / 4) * 4];
        a.x += e.x; a.y += e.y; a.z += e.z; a.w += e.w;
    }
    *(float4*)&g_v[(size_t)i * DD + q * 4] = a;
}

// v[dst] += attr[src]  over all edges (64 float4 chunks per edge)
__global__ void k_scatter_attr(const int* __restrict__ src,
                               const int* __restrict__ dst, int m) {
    int idx = blockIdx.x * blockDim.x + threadIdx.x;
    int e = idx >> 6;
    int q = idx & 63;
    if (e >= m) return;
    int s  = __ldg(&src[e]);
    int d2 = __ldg(&dst[e]);
    float4 a = *(const float4*)&g_attr[(size_t)s * DD + q * 4];
    float* p = &g_v[(size_t)d2 * DD + q * 4];
    atomicAdd(p + 0, a.x); atomicAdd(p + 1, a.y);
    atomicAdd(p + 2, a.z); atomicAdd(p + 3, a.w);
}

// ---------------- inner GEMM: g_attr = g_v @ W + b  (N x 256 x 256) ----------------
__global__ void __launch_bounds__(256) k_inner(const float* __restrict__ W,
                                               const float* __restrict__ bias, int n) {
    __shared__ float sA[16][64];   // A transposed: sA[k][m]
    __shared__ float sB[16][64];
    int tid = threadIdx.x;
    int cx = tid & 15;             // col group (4 cols)
    int cy = tid >> 4;             // row group (4 rows)
    int row0 = blockIdx.x * 64;
    int col0 = blockIdx.y * 64;
    float acc[4][4] = {};

    int lr = tid >> 2;             // A load: row within tile
    int lk = (tid & 3) << 2;       // A load: k quad
    int bk = tid >> 4;             // B load: k row
    int bc = (tid & 15) << 2;      // B load: col quad

    for (int k0 = 0; k0 < DD; k0 += 16) {
        float4 a4 = make_float4(0.f, 0.f, 0.f, 0.f);
        int grow = row0 + lr;
        if (grow < n) a4 = *(const float4*)&g_v[(size_t)grow * DD + k0 + lk];
        float4 b4 = *(const float4*)&W[(size_t)(k0 + bk) * DD + col0 + bc];
        __syncthreads();
        sA[lk + 0][lr] = a4.x; sA[lk + 1][lr] = a4.y;
        sA[lk + 2][lr] = a4.z; sA[lk + 3][lr] = a4.w;
        *(float4*)&sB[bk][bc] = b4;
        __syncthreads();
#pragma unroll
        for (int kk = 0; kk < 16; ++kk) {
            float4 av = *(float4*)&sA[kk][cy * 4];
            float4 bv = *(float4*)&sB[kk][cx * 4];
            acc[0][0] += av.x * bv.x; acc[0][1] += av.x * bv.y; acc[0][2] += av.x * bv.z; acc[0][3] += av.x * bv.w;
            acc[1][0] += av.y * bv.x; acc[1][1] += av.y * bv.y; acc[1][2] += av.y * bv.z; acc[1][3] += av.y * bv.w;
            acc[2][0] += av.z * bv.x; acc[2][1] += av.z * bv.y; acc[2][2] += av.z * bv.z; acc[2][3] += av.z * bv.w;
            acc[3][0] += av.w * bv.x; acc[3][1] += av.w * bv.y; acc[3][2] += av.w * bv.z; acc[3][3] += av.w * bv.w;
        }
    }
    float4 bb = *(const float4*)&bias[col0 + cx * 4];
#pragma unroll
    for (int i = 0; i < 4; ++i) {
        int row = row0 + cy * 4 + i;
        if (row < n) {
            float4 o = make_float4(acc[i][0] + bb.x, acc[i][1] + bb.y,
                                   acc[i][2] + bb.z, acc[i][3] + bb.w);
            *(float4*)&g_attr[(size_t)row * DD + col0 + cx * 4] = o;
        }
    }
}

// ---------------- fused fingerprint: softmax(attr@W + b) summed over rows ----------------
// Block: 16 rows x 2048 cols. Per-thread tile: 16 rows x 4 cols (A is warp-broadcast).
// f32x2 FFMA2 inner loop, A stored duplicated (a,a) in smem, B register-prefetched.
#define FTM 16
#define FTN 1024
#define FBK 8
#define FP_SMEM_FLOATS (FTM * OUTF + DD * FTM * 2 + FBK * FTN + FTM)

__global__ void __launch_bounds__(256, 1)
k_fp(const float* __restrict__ W,      // [DD][OUTF]
     const float* __restrict__ bias,   // [OUTF]
     float* __restrict__ fp_out, int n) {
    extern __shared__ float sm[];
    float* sLog = sm;                          // FTM*OUTF floats (128 KB)
    float* sAd  = sLog + FTM * OUTF;           // DD*FTM float2-dup (32 KB)
    float* sB   = sAd + DD * FTM * 2;          // FBK*FTN floats (32 KB)
    float* sInv = sB + FBK * FTN;              // FTM floats

    int tid = threadIdx.x;
    int row0 = blockIdx.x * FTM;

    // load A rows, duplicated (a,a) pairs, transposed: sAd[k][m] = {a,a}
    for (int i = tid; i < FTM * DD; i += 256) {
        int mrow = i >> 8;        // i / 256
        int k    = i & 255;
        float v = 0.f;
        if (row0 + mrow < n) v = g_attr[(size_t)(row0 + mrow) * DD + k];
        ((float2*)sAd)[k * FTM + mrow] = make_float2(v, v);
    }
    __syncthreads();

#pragma unroll 1
    for (int nt = 0; nt < OUTF / FTN; ++nt) {
        unsigned long long acc[FTM][2];
#pragma unroll
        for (int i = 0; i < FTM; ++i) { acc[i][0] = 0ULL; acc[i][1] = 0ULL; }

        // prefetch B slice k0=0  (FTN/4 == 256 == blockDim: thread tid owns col4 tid of row j)
        float4 pre[FBK];
#pragma unroll
        for (int j = 0; j < FBK; ++j)
            pre[j] = *(const float4*)&W[(size_t)j * OUTF + nt * FTN + tid * 4];

        for (int k0 = 0; k0 < DD; k0 += FBK) {
            __syncthreads();   // previous slice fully consumed
#pragma unroll
            for (int j = 0; j < FBK; ++j)
                *(float4*)&sB[j * FTN + tid * 4] = pre[j];
            __syncthreads();
            if (k0 + FBK < DD) {
#pragma unroll
                for (int j = 0; j < FBK; ++j)
                    pre[j] = *(const float4*)&W[(size_t)(k0 + FBK + j) * OUTF + nt * FTN + tid * 4];
            }
#pragma unroll
            for (int kk = 0; kk < FBK; ++kk) {
                ulonglong2 b2 = *(const ulonglong2*)&sB[kk * FTN + tid * 4];
                const ulonglong2* ap =
                    reinterpret_cast<const ulonglong2*>(sAd) + (size_t)(k0 + kk) * (FTM / 2);
#pragma unroll
                for (int mp = 0; mp < FTM / 2; ++mp) {
                    ulonglong2 a2 = ap[mp];   // dup pairs for rows 2mp, 2mp+1 (warp-broadcast)
                    acc[2 * mp + 0][0] = fma2(a2.x, b2.x, acc[2 * mp + 0][0]);
                    acc[2 * mp + 0][1] = fma2(a2.x, b2.y, acc[2 * mp + 0][1]);
                    acc[2 * mp + 1][0] = fma2(a2.y, b2.x, acc[2 * mp + 1][0]);
                    acc[2 * mp + 1][1] = fma2(a2.y, b2.y, acc[2 * mp + 1][1]);
                }
            }
        }
        // epilogue: logits + bias -> smem
        float4 bb = *(const float4*)&bias[nt * FTN + tid * 4];
#pragma unroll
        for (int m2 = 0; m2 < FTM; ++m2) {
            float2 lo = u2f(acc[m2][0]);
            float2 hi = u2f(acc[m2][1]);
            float4 z = make_float4(lo.x + bb.x, lo.y + bb.y, hi.x + bb.z, hi.y + bb.w);
            *(float4*)&sLog[(size_t)m2 * OUTF + nt * FTN + tid * 4] = z;
        }
    }
    __syncthreads();

    // softmax per row: warp w handles rows w and w+8
    int lane = tid & 31;
    int wrp  = tid >> 5;
#pragma unroll
    for (int rr = 0; rr < 2; ++rr) {
        int r = wrp + rr * 8;
        float mx = -1e30f;
        for (int c = lane; c < OUTF; c += 32)
            mx = fmaxf(mx, sLog[(size_t)r * OUTF + c]);
#pragma unroll
        for (int o = 16; o > 0; o >>= 1)
            mx = fmaxf(mx, __shfl_xor_sync(0xFFFFFFFFu, mx, o));
        float s = 0.f;
        for (int c = lane; c < OUTF; c += 32) {
            float e = __expf(sLog[(size_t)r * OUTF + c] - mx);
            sLog[(size_t)r * OUTF + c] = e;
            s += e;
        }
#pragma unroll
        for (int o = 16; o > 0; o >>= 1)
            s += __shfl_xor_sync(0xFFFFFFFFu, s, o);
        if (lane == 0) sInv[r] = (row0 + r < n) ? (1.f / s) : 0.f;
    }
    __syncthreads();

    // column sums over the 16 rows -> one atomicAdd per column per block
    for (int c = tid; c < OUTF; c += 256) {
        float s = 0.f;
#pragma unroll
        for (int r = 0; r < FTM; ++r)
            s += sLog[(size_t)r * OUTF + c] * sInv[r];
        atomicAdd(&fp_out[c], s);
    }
}

// ---------------- launch ----------------
extern "C" void kernel_launch(void* const* d_in, const int* in_sizes, int n_in,
                              void* d_out, int out_size) {
    const float* node_attr = (const float*)d_in[0];
    const float* edge_attr = (const float*)d_in[1];
    const int*   esrc      = (const int*)d_in[2];
    const int*   edst      = (const int*)d_in[3];
    const float* W_inner   = (const float*)d_in[4];
    const float* b_inner   = (const float*)d_in[5];
    const float* W_output  = (const float*)d_in[6];
    const float* b_output  = (const float*)d_in[7];
    float* out = (float*)d_out;

    int n = in_sizes[0] / NODE_F;   // 50000
    int m = in_sizes[2];            // 800000

    const int fp_smem = FP_SMEM_FLOATS * (int)sizeof(float);  // ~196.7 KB
    cudaFuncSetAttribute(k_fp, cudaFuncAttributeMaxDynamicSharedMemorySize, fp_smem);

    int nq = n * (DD / 4);          // n*64 float4 chunks per node-row pass
    k_zero<<<(nq + 255) / 256, 256>>>(out, n);
    k_init_attr<<<(nq + 255) / 256, 256>>>(node_attr, n);
    k_scatter_edge<<<(m * (EDGE_F / 4) + 255) / 256, 256>>>(edge_attr, edst, m);

    // depth 0 fingerprint
    k_fp<<<(n + FTM - 1) / FTM, 256, fp_smem>>>(W_output, b_output, out, n);

    for (int d = 1; d <= 3; ++d) {
        k_vinit<<<(nq + 255) / 256, 256>>>(n);
        k_scatter_attr<<<(m * (DD / 4) + 255) / 256, 256>>>(esrc, edst, m);
        k_inner<<<dim3((n + 63) / 64, DD / 64), 256>>>(
            W_inner + (size_t)(d - 1) * DD * DD, b_inner + (size_t)(d - 1) * DD, n);
        k_fp<<<(n + FTM - 1) / FTM, 256, fp_smem>>>(
            W_output + (size_t)d * DD * OUTF, b_output + (size_t)d * OUTF, out, n);
    }
}

// round 10
// speedup vs baseline: 1.0004x; 1.0004x over previous
#include <cuda_runtime.h>

// ---------------- problem constants ----------------
#define NODE_F 192
#define EDGE_F 64
#define DD     256          // inner dim
#define OUTF   2048
#define N_MAX  50000
#define M_MAX  800000

// ---------------- device scratch (no allocs allowed) ----------------
__device__ float g_attr[(size_t)N_MAX * DD];   // 51.2 MB
__device__ float g_v   [(size_t)N_MAX * DD];   // 51.2 MB
__device__ float g_eagg[(size_t)N_MAX * EDGE_F]; // 12.8 MB

// ---------------- f32x2 helpers (FFMA2) ----------------
__device__ __forceinline__ unsigned long long fma2(unsigned long long a,
                                                   unsigned long long b,
                                                   unsigned long long c) {
    unsigned long long d;
    asm("fma.rn.f32x2 %0, %1, %2, %3;" : "=l"(d) : "l"(a), "l"(b), "l"(c));
    return d;
}
__device__ __forceinline__ float2 u2f(unsigned long long u) {
    float2 f;
    asm("mov.b64 {%0, %1}, %2;" : "=f"(f.x), "=f"(f.y) : "l"(u));
    return f;
}

// ---------------- misc kernels ----------------
__global__ void k_zero(float* __restrict__ out, int n) {
    int idx = blockIdx.x * blockDim.x + threadIdx.x;
    if (idx < OUTF) out[idx] = 0.f;
    if (idx < n * EDGE_F) g_eagg[idx] = 0.f;
}

// attr = [node_attr | zeros], float4 granularity (192 % 4 == 0)
__global__ void k_init_attr(const float* __restrict__ node, int n) {
    int idx = blockIdx.x * blockDim.x + threadIdx.x;
    if (idx >= n * (DD / 4)) return;
    int i = idx >> 6;        // node
    int q = idx & 63;        // float4 chunk within row
    float4 v;
    if (q * 4 < NODE_F) v = *(const float4*)&node[(size_t)i * NODE_F + q * 4];
    else                v = make_float4(0.f, 0.f, 0.f, 0.f);
    *(float4*)&g_attr[(size_t)i * DD + q * 4] = v;
}

// precompute once per launch: g_eagg[dst] += edge_attr[e]  (the attr-independent part)
__global__ void k_scatter_edge(const float* __restrict__ eattr,
                               const int* __restrict__ dst, int m) {
    int idx = blockIdx.x * blockDim.x + threadIdx.x;
    if (idx >= m * (EDGE_F / 4)) return;
    int e = idx >> 4;
    int q = idx & 15;
    float4 a = *(const float4*)&eattr[(size_t)e * EDGE_F + q * 4];
    int d2 = __ldg(&dst[e]);
    float* p = &g_eagg[(size_t)d2 * EDGE_F + q * 4];
    atomicAdd(p + 0, a.x); atomicAdd(p + 1, a.y);
    atomicAdd(p + 2, a.z); atomicAdd(p + 3, a.w);
}

// v = attr (+ eagg on last 64 features)
__global__ void k_vinit(int n) {
    int idx = blockIdx.x * blockDim.x + threadIdx.x;
    if (idx >= n * (DD / 4)) return;
    int i = idx >> 6;
    int q = idx & 63;
    float4 a = *(const float4*)&g_attr[(size_t)i * DD + q * 4];
    if (q >= NODE_F / 4) {
        float4 e = *(const float4*)&g_eagg[(size_t)i * EDGE_F + (q - NODE_F / 4) * 4];
        a.x += e.x; a.y += e.y; a.z += e.z; a.w += e.w;
    }
    *(float4*)&g_v[(size_t)i * DD + q * 4] = a;
}

// v[dst] += attr[src]  over all edges (64 float4 chunks per edge)
__global__ void k_scatter_attr(const int* __restrict__ src,
                               const int* __restrict__ dst, int m) {
    int idx = blockIdx.x * blockDim.x + threadIdx.x;
    int e = idx >> 6;
    int q = idx & 63;
    if (e >= m) return;
    int s  = __ldg(&src[e]);
    int d2 = __ldg(&dst[e]);
    float4 a = *(const float4*)&g_attr[(size_t)s * DD + q * 4];
    float* p = &g_v[(size_t)d2 * DD + q * 4];
    atomicAdd(p + 0, a.x); atomicAdd(p + 1, a.y);
    atomicAdd(p + 2, a.z); atomicAdd(p + 3, a.w);
}

// ---------------- inner GEMM: g_attr = g_v @ W + b  (N x 256 x 256) ----------------
__global__ void __launch_bounds__(256) k_inner(const float* __restrict__ W,
                                               const float* __restrict__ bias, int n) {
    __shared__ float sA[16][64];   // A transposed: sA[k][m]
    __shared__ float sB[16][64];
    int tid = threadIdx.x;
    int cx = tid & 15;             // col group (4 cols)
    int cy = tid >> 4;             // row group (4 rows)
    int row0 = blockIdx.x * 64;
    int col0 = blockIdx.y * 64;
    float acc[4][4] = {};

    int lr = tid >> 2;             // A load: row within tile
    int lk = (tid & 3) << 2;       // A load: k quad
    int bk = tid >> 4;             // B load: k row
    int bc = (tid & 15) << 2;      // B load: col quad

    for (int k0 = 0; k0 < DD; k0 += 16) {
        float4 a4 = make_float4(0.f, 0.f, 0.f, 0.f);
        int grow = row0 + lr;
        if (grow < n) a4 = *(const float4*)&g_v[(size_t)grow * DD + k0 + lk];
        float4 b4 = *(const float4*)&W[(size_t)(k0 + bk) * DD + col0 + bc];
        __syncthreads();
        sA[lk + 0][lr] = a4.x; sA[lk + 1][lr] = a4.y;
        sA[lk + 2][lr] = a4.z; sA[lk + 3][lr] = a4.w;
        *(float4*)&sB[bk][bc] = b4;
        __syncthreads();
#pragma unroll
        for (int kk = 0; kk < 16; ++kk) {
            float4 av = *(float4*)&sA[kk][cy * 4];
            float4 bv = *(float4*)&sB[kk][cx * 4];
            acc[0][0] += av.x * bv.x; acc[0][1] += av.x * bv.y; acc[0][2] += av.x * bv.z; acc[0][3] += av.x * bv.w;
            acc[1][0] += av.y * bv.x; acc[1][1] += av.y * bv.y; acc[1][2] += av.y * bv.z; acc[1][3] += av.y * bv.w;
            acc[2][0] += av.z * bv.x; acc[2][1] += av.z * bv.y; acc[2][2] += av.z * bv.z; acc[2][3] += av.z * bv.w;
            acc[3][0] += av.w * bv.x; acc[3][1] += av.w * bv.y; acc[3][2] += av.w * bv.z; acc[3][3] += av.w * bv.w;
        }
    }
    float4 bb = *(const float4*)&bias[col0 + cx * 4];
#pragma unroll
    for (int i = 0; i < 4; ++i) {
        int row = row0 + cy * 4 + i;
        if (row < n) {
            float4 o = make_float4(acc[i][0] + bb.x, acc[i][1] + bb.y,
                                   acc[i][2] + bb.z, acc[i][3] + bb.w);
            *(float4*)&g_attr[(size_t)row * DD + col0 + cx * 4] = o;
        }
    }
}

// ---------------- fused fingerprint: softmax(attr@W + b) summed over rows ----------------
// Block: 16 rows x 2048 cols. Per-thread tile: 16 rows x 4 cols (A is warp-broadcast).
// f32x2 FFMA2 inner loop, A stored duplicated (a,a) in smem, B register-prefetched.
#define FTM 16
#define FTN 1024
#define FBK 8
#define FP_SMEM_FLOATS (FTM * OUTF + DD * FTM * 2 + FBK * FTN + FTM)

__global__ void __launch_bounds__(256, 1)
k_fp(const float* __restrict__ W,      // [DD][OUTF]
     const float* __restrict__ bias,   // [OUTF]
     float* __restrict__ fp_out, int n) {
    extern __shared__ float sm[];
    float* sLog = sm;                          // FTM*OUTF floats (128 KB)
    float* sAd  = sLog + FTM * OUTF;           // DD*FTM float2-dup (32 KB)
    float* sB   = sAd + DD * FTM * 2;          // FBK*FTN floats (32 KB)
    float* sInv = sB + FBK * FTN;              // FTM floats

    int tid = threadIdx.x;
    int row0 = blockIdx.x * FTM;

    // load A rows, duplicated (a,a) pairs, transposed: sAd[k][m] = {a,a}
    for (int i = tid; i < FTM * DD; i += 256) {
        int mrow = i >> 8;        // i / 256
        int k    = i & 255;
        float v = 0.f;
        if (row0 + mrow < n) v = g_attr[(size_t)(row0 + mrow) * DD + k];
        ((float2*)sAd)[k * FTM + mrow] = make_float2(v, v);
    }
    __syncthreads();

#pragma unroll 1
    for (int nt = 0; nt < OUTF / FTN; ++nt) {
        unsigned long long acc[FTM][2];
#pragma unroll
        for (int i = 0; i < FTM; ++i) { acc[i][0] = 0ULL; acc[i][1] = 0ULL; }

        // prefetch B slice k0=0  (FTN/4 == 256 == blockDim: thread tid owns col4 tid of row j)
        float4 pre[FBK];
#pragma unroll
        for (int j = 0; j < FBK; ++j)
            pre[j] = *(const float4*)&W[(size_t)j * OUTF + nt * FTN + tid * 4];

        for (int k0 = 0; k0 < DD; k0 += FBK) {
            __syncthreads();   // previous slice fully consumed
#pragma unroll
            for (int j = 0; j < FBK; ++j)
                *(float4*)&sB[j * FTN + tid * 4] = pre[j];
            __syncthreads();
            if (k0 + FBK < DD) {
#pragma unroll
                for (int j = 0; j < FBK; ++j)
                    pre[j] = *(const float4*)&W[(size_t)(k0 + FBK + j) * OUTF + nt * FTN + tid * 4];
            }
#pragma unroll
            for (int kk = 0; kk < FBK; ++kk) {
                ulonglong2 b2 = *(const ulonglong2*)&sB[kk * FTN + tid * 4];
                const ulonglong2* ap =
                    reinterpret_cast<const ulonglong2*>(sAd) + (size_t)(k0 + kk) * (FTM / 2);
#pragma unroll
                for (int mp = 0; mp < FTM / 2; ++mp) {
                    ulonglong2 a2 = ap[mp];   // dup pairs for rows 2mp, 2mp+1 (warp-broadcast)
                    acc[2 * mp + 0][0] = fma2(a2.x, b2.x, acc[2 * mp + 0][0]);
                    acc[2 * mp + 0][1] = fma2(a2.x, b2.y, acc[2 * mp + 0][1]);
                    acc[2 * mp + 1][0] = fma2(a2.y, b2.x, acc[2 * mp + 1][0]);
                    acc[2 * mp + 1][1] = fma2(a2.y, b2.y, acc[2 * mp + 1][1]);
                }
            }
        }
        // epilogue: logits + bias -> smem
        float4 bb = *(const float4*)&bias[nt * FTN + tid * 4];
#pragma unroll
        for (int m2 = 0; m2 < FTM; ++m2) {
            float2 lo = u2f(acc[m2][0]);
            float2 hi = u2f(acc[m2][1]);
            float4 z = make_float4(lo.x + bb.x, lo.y + bb.y, hi.x + bb.z, hi.y + bb.w);
            *(float4*)&sLog[(size_t)m2 * OUTF + nt * FTN + tid * 4] = z;
        }
    }
    __syncthreads();

    // softmax per row: warp w handles rows w and w+8
    int lane = tid & 31;
    int wrp  = tid >> 5;
#pragma unroll
    for (int rr = 0; rr < 2; ++rr) {
        int r = wrp + rr * 8;
        float mx = -1e30f;
        for (int c = lane; c < OUTF; c += 32)
            mx = fmaxf(mx, sLog[(size_t)r * OUTF + c]);
#pragma unroll
        for (int o = 16; o > 0; o >>= 1)
            mx = fmaxf(mx, __shfl_xor_sync(0xFFFFFFFFu, mx, o));
        float s = 0.f;
        for (int c = lane; c < OUTF; c += 32) {
            float e = __expf(sLog[(size_t)r * OUTF + c] - mx);
            sLog[(size_t)r * OUTF + c] = e;
            s += e;
        }
#pragma unroll
        for (int o = 16; o > 0; o >>= 1)
            s += __shfl_xor_sync(0xFFFFFFFFu, s, o);
        if (lane == 0) sInv[r] = (row0 + r < n) ? (1.f / s) : 0.f;
    }
    __syncthreads();

    // column sums over the 16 rows -> one atomicAdd per column per block
    for (int c = tid; c < OUTF; c += 256) {
        float s = 0.f;
#pragma unroll
        for (int r = 0; r < FTM; ++r)
            s += sLog[(size_t)r * OUTF + c] * sInv[r];
        atomicAdd(&fp_out[c], s);
    }
}

// ---------------- launch ----------------
extern "C" void kernel_launch(void* const* d_in, const int* in_sizes, int n_in,
                              void* d_out, int out_size) {
    const float* node_attr = (const float*)d_in[0];
    const float* edge_attr = (const float*)d_in[1];
    const int*   esrc      = (const int*)d_in[2];
    const int*   edst      = (const int*)d_in[3];
    const float* W_inner   = (const float*)d_in[4];
    const float* b_inner   = (const float*)d_in[5];
    const float* W_output  = (const float*)d_in[6];
    const float* b_output  = (const float*)d_in[7];
    float* out = (float*)d_out;

    int n = in_sizes[0] / NODE_F;   // 50000
    int m = in_sizes[2];            // 800000

    const int fp_smem = FP_SMEM_FLOATS * (int)sizeof(float);  // ~196.7 KB
    cudaFuncSetAttribute(k_fp, cudaFuncAttributeMaxDynamicSharedMemorySize, fp_smem);

    int nq = n * (DD / 4);          // n*64 float4 chunks per node-row pass
    k_zero<<<(nq + 255) / 256, 256>>>(out, n);
    k_init_attr<<<(nq + 255) / 256, 256>>>(node_attr, n);
    k_scatter_edge<<<(m * (EDGE_F / 4) + 255) / 256, 256>>>(edge_attr, edst, m);

    // depth 0 fingerprint
    k_fp<<<(n + FTM - 1) / FTM, 256, fp_smem>>>(W_output, b_output, out, n);

    for (int d = 1; d <= 3; ++d) {
        k_vinit<<<(nq + 255) / 256, 256>>>(n);
        k_scatter_attr<<<(m * (DD / 4) + 255) / 256, 256>>>(esrc, edst, m);
        k_inner<<<dim3((n + 63) / 64, DD / 64), 256>>>(
            W_inner + (size_t)(d - 1) * DD * DD, b_inner + (size_t)(d - 1) * DD, n);
        k_fp<<<(n + FTM - 1) / FTM, 256, fp_smem>>>(
            W_output + (size_t)d * DD * OUTF, b_output + (size_t)d * OUTF, out, n);
    }
}

// round 11
// speedup vs baseline: 1.0028x; 1.0024x over previous
#include <cuda_runtime.h>

// ---------------- problem constants ----------------
#define NODE_F 192
#define EDGE_F 64
#define DD     256          // inner dim
#define OUTF   2048
#define N_MAX  50000
#define M_MAX  800000

// ---------------- device scratch (no allocs allowed) ----------------
__device__ float g_attr[(size_t)N_MAX * DD];   // 51.2 MB
__device__ float g_v   [(size_t)N_MAX * DD];   // 51.2 MB
__device__ float g_eagg[(size_t)N_MAX * EDGE_F]; // 12.8 MB

// ---------------- f32x2 helpers (FFMA2) ----------------
__device__ __forceinline__ unsigned long long fma2(unsigned long long a,
                                                   unsigned long long b,
                                                   unsigned long long c) {
    unsigned long long d;
    asm("fma.rn.f32x2 %0, %1, %2, %3;" : "=l"(d) : "l"(a), "l"(b), "l"(c));
    return d;
}
__device__ __forceinline__ float2 u2f(unsigned long long u) {
    float2 f;
    asm("mov.b64 {%0, %1}, %2;" : "=f"(f.x), "=f"(f.y) : "l"(u));
    return f;
}

// ---------------- misc kernels ----------------
__global__ void k_zero(float* __restrict__ out, int n) {
    int idx = blockIdx.x * blockDim.x + threadIdx.x;
    if (idx < OUTF) out[idx] = 0.f;
    if (idx < n * EDGE_F) g_eagg[idx] = 0.f;
}

// attr = [node_attr | zeros], float4 granularity (192 % 4 == 0)
__global__ void k_init_attr(const float* __restrict__ node, int n) {
    int idx = blockIdx.x * blockDim.x + threadIdx.x;
    if (idx >= n * (DD / 4)) return;
    int i = idx >> 6;        // node
    int q = idx & 63;        // float4 chunk within row
    float4 v;
    if (q * 4 < NODE_F) v = *(const float4*)&node[(size_t)i * NODE_F + q * 4];
    else                v = make_float4(0.f, 0.f, 0.f, 0.f);
    *(float4*)&g_attr[(size_t)i * DD + q * 4] = v;
}

// precompute once per launch: g_eagg[dst] += edge_attr[e]  (the attr-independent part)
__global__ void k_scatter_edge(const float* __restrict__ eattr,
                               const int* __restrict__ dst, int m) {
    int idx = blockIdx.x * blockDim.x + threadIdx.x;
    if (idx >= m * (EDGE_F / 4)) return;
    int e = idx >> 4;
    int q = idx & 15;
    float4 a = *(const float4*)&eattr[(size_t)e * EDGE_F + q * 4];
    int d2 = __ldg(&dst[e]);
    float* p = &g_eagg[(size_t)d2 * EDGE_F + q * 4];
    atomicAdd(p + 0, a.x); atomicAdd(p + 1, a.y);
    atomicAdd(p + 2, a.z); atomicAdd(p + 3, a.w);
}

// v = attr (+ eagg on last 64 features)
__global__ void k_vinit(int n) {
    int idx = blockIdx.x * blockDim.x + threadIdx.x;
    if (idx >= n * (DD / 4)) return;
    int i = idx >> 6;
    int q = idx & 63;
    float4 a = *(const float4*)&g_attr[(size_t)i * DD + q * 4];
    if (q >= NODE_F / 4) {
        float4 e = *(const float4*)&g_eagg[(size_t)i * EDGE_F + (q - NODE_F / 4) * 4];
        a.x += e.x; a.y += e.y; a.z += e.z; a.w += e.w;
    }
    *(float4*)&g_v[(size_t)i * DD + q * 4] = a;
}

// v[dst] += attr[src]  over all edges (64 float4 chunks per edge)
__global__ void k_scatter_attr(const int* __restrict__ src,
                               const int* __restrict__ dst, int m) {
    int idx = blockIdx.x * blockDim.x + threadIdx.x;
    int e = idx >> 6;
    int q = idx & 63;
    if (e >= m) return;
    int s  = __ldg(&src[e]);
    int d2 = __ldg(&dst[e]);
    float4 a = *(const float4*)&g_attr[(size_t)s * DD + q * 4];
    float* p = &g_v[(size_t)d2 * DD + q * 4];
    atomicAdd(p + 0, a.x); atomicAdd(p + 1, a.y);
    atomicAdd(p + 2, a.z); atomicAdd(p + 3, a.w);
}

// ---------------- inner GEMM: g_attr = g_v @ W + b  (N x 256 x 256) ----------------
__global__ void __launch_bounds__(256) k_inner(const float* __restrict__ W,
                                               const float* __restrict__ bias, int n) {
    __shared__ float sA[16][64];   // A transposed: sA[k][m]
    __shared__ float sB[16][64];
    int tid = threadIdx.x;
    int cx = tid & 15;             // col group (4 cols)
    int cy = tid >> 4;             // row group (4 rows)
    int row0 = blockIdx.x * 64;
    int col0 = blockIdx.y * 64;
    float acc[4][4] = {};

    int lr = tid >> 2;             // A load: row within tile
    int lk = (tid & 3) << 2;       // A load: k quad
    int bk = tid >> 4;             // B load: k row
    int bc = (tid & 15) << 2;      // B load: col quad

    for (int k0 = 0; k0 < DD; k0 += 16) {
        float4 a4 = make_float4(0.f, 0.f, 0.f, 0.f);
        int grow = row0 + lr;
        if (grow < n) a4 = *(const float4*)&g_v[(size_t)grow * DD + k0 + lk];
        float4 b4 = *(const float4*)&W[(size_t)(k0 + bk) * DD + col0 + bc];
        __syncthreads();
        sA[lk + 0][lr] = a4.x; sA[lk + 1][lr] = a4.y;
        sA[lk + 2][lr] = a4.z; sA[lk + 3][lr] = a4.w;
        *(float4*)&sB[bk][bc] = b4;
        __syncthreads();
#pragma unroll
        for (int kk = 0; kk < 16; ++kk) {
            float4 av = *(float4*)&sA[kk][cy * 4];
            float4 bv = *(float4*)&sB[kk][cx * 4];
            acc[0][0] += av.x * bv.x; acc[0][1] += av.x * bv.y; acc[0][2] += av.x * bv.z; acc[0][3] += av.x * bv.w;
            acc[1][0] += av.y * bv.x; acc[1][1] += av.y * bv.y; acc[1][2] += av.y * bv.z; acc[1][3] += av.y * bv.w;
            acc[2][0] += av.z * bv.x; acc[2][1] += av.z * bv.y; acc[2][2] += av.z * bv.z; acc[2][3] += av.z * bv.w;
            acc[3][0] += av.w * bv.x; acc[3][1] += av.w * bv.y; acc[3][2] += av.w * bv.z; acc[3][3] += av.w * bv.w;
        }
    }
    float4 bb = *(const float4*)&bias[col0 + cx * 4];
#pragma unroll
    for (int i = 0; i < 4; ++i) {
        int row = row0 + cy * 4 + i;
        if (row < n) {
            float4 o = make_float4(acc[i][0] + bb.x, acc[i][1] + bb.y,
                                   acc[i][2] + bb.z, acc[i][3] + bb.w);
            *(float4*)&g_attr[(size_t)row * DD + col0 + cx * 4] = o;
        }
    }
}

// ---------------- fused fingerprint: softmax(attr@W + b) summed over rows ----------------
// Block: 16 rows x 2048 cols. Per-thread tile: 16 rows x 4 cols (A is warp-broadcast).
// f32x2 FFMA2 inner loop, A stored duplicated (a,a) in smem, B register-prefetched.
#define FTM 16
#define FTN 1024
#define FBK 8
#define FP_SMEM_FLOATS (FTM * OUTF + DD * FTM * 2 + FBK * FTN + FTM)

__global__ void __launch_bounds__(256, 1)
k_fp(const float* __restrict__ W,      // [DD][OUTF]
     const float* __restrict__ bias,   // [OUTF]
     float* __restrict__ fp_out, int n) {
    extern __shared__ float sm[];
    float* sLog = sm;                          // FTM*OUTF floats (128 KB)
    float* sAd  = sLog + FTM * OUTF;           // DD*FTM float2-dup (32 KB)
    float* sB   = sAd + DD * FTM * 2;          // FBK*FTN floats (32 KB)
    float* sInv = sB + FBK * FTN;              // FTM floats

    int tid = threadIdx.x;
    int row0 = blockIdx.x * FTM;

    // load A rows, duplicated (a,a) pairs, transposed: sAd[k][m] = {a,a}
    for (int i = tid; i < FTM * DD; i += 256) {
        int mrow = i >> 8;        // i / 256
        int k    = i & 255;
        float v = 0.f;
        if (row0 + mrow < n) v = g_attr[(size_t)(row0 + mrow) * DD + k];
        ((float2*)sAd)[k * FTM + mrow] = make_float2(v, v);
    }
    __syncthreads();

#pragma unroll 1
    for (int nt = 0; nt < OUTF / FTN; ++nt) {
        unsigned long long acc[FTM][2];
#pragma unroll
        for (int i = 0; i < FTM; ++i) { acc[i][0] = 0ULL; acc[i][1] = 0ULL; }

        // prefetch B slice k0=0  (FTN/4 == 256 == blockDim: thread tid owns col4 tid of row j)
        float4 pre[FBK];
#pragma unroll
        for (int j = 0; j < FBK; ++j)
            pre[j] = *(const float4*)&W[(size_t)j * OUTF + nt * FTN + tid * 4];

        for (int k0 = 0; k0 < DD; k0 += FBK) {
            __syncthreads();   // previous slice fully consumed
#pragma unroll
            for (int j = 0; j < FBK; ++j)
                *(float4*)&sB[j * FTN + tid * 4] = pre[j];
            __syncthreads();
            if (k0 + FBK < DD) {
#pragma unroll
                for (int j = 0; j < FBK; ++j)
                    pre[j] = *(const float4*)&W[(size_t)(k0 + FBK + j) * OUTF + nt * FTN + tid * 4];
            }
#pragma unroll
            for (int kk = 0; kk < FBK; ++kk) {
                ulonglong2 b2 = *(const ulonglong2*)&sB[kk * FTN + tid * 4];
                const ulonglong2* ap =
                    reinterpret_cast<const ulonglong2*>(sAd) + (size_t)(k0 + kk) * (FTM / 2);
#pragma unroll
                for (int mp = 0; mp < FTM / 2; ++mp) {
                    ulonglong2 a2 = ap[mp];   // dup pairs for rows 2mp, 2mp+1 (warp-broadcast)
                    acc[2 * mp + 0][0] = fma2(a2.x, b2.x, acc[2 * mp + 0][0]);
                    acc[2 * mp + 0][1] = fma2(a2.x, b2.y, acc[2 * mp + 0][1]);
                    acc[2 * mp + 1][0] = fma2(a2.y, b2.x, acc[2 * mp + 1][0]);
                    acc[2 * mp + 1][1] = fma2(a2.y, b2.y, acc[2 * mp + 1][1]);
                }
            }
        }
        // epilogue: logits + bias -> smem
        float4 bb = *(const float4*)&bias[nt * FTN + tid * 4];
#pragma unroll
        for (int m2 = 0; m2 < FTM; ++m2) {
            float2 lo = u2f(acc[m2][0]);
            float2 hi = u2f(acc[m2][1]);
            float4 z = make_float4(lo.x + bb.x, lo.y + bb.y, hi.x + bb.z, hi.y + bb.w);
            *(float4*)&sLog[(size_t)m2 * OUTF + nt * FTN + tid * 4] = z;
        }
    }
    __syncthreads();

    // softmax per row: warp w handles rows w and w+8
    int lane = tid & 31;
    int wrp  = tid >> 5;
#pragma unroll
    for (int rr = 0; rr < 2; ++rr) {
        int r = wrp + rr * 8;
        float mx = -1e30f;
        for (int c = lane; c < OUTF; c += 32)
            mx = fmaxf(mx, sLog[(size_t)r * OUTF + c]);
#pragma unroll
        for (int o = 16; o > 0; o >>= 1)
            mx = fmaxf(mx, __shfl_xor_sync(0xFFFFFFFFu, mx, o));
        float s = 0.f;
        for (int c = lane; c < OUTF; c += 32) {
            float e = __expf(sLog[(size_t)r * OUTF + c] - mx);
            sLog[(size_t)r * OUTF + c] = e;
            s += e;
        }
#pragma unroll
        for (int o = 16; o > 0; o >>= 1)
            s += __shfl_xor_sync(0xFFFFFFFFu, s, o);
        if (lane == 0) sInv[r] = (row0 + r < n) ? (1.f / s) : 0.f;
    }
    __syncthreads();

    // column sums over the 16 rows -> one atomicAdd per column per block
    for (int c = tid; c < OUTF; c += 256) {
        float s = 0.f;
#pragma unroll
        for (int r = 0; r < FTM; ++r)
            s += sLog[(size_t)r * OUTF + c] * sInv[r];
        atomicAdd(&fp_out[c], s);
    }
}

// ---------------- launch ----------------
extern "C" void kernel_launch(void* const* d_in, const int* in_sizes, int n_in,
                              void* d_out, int out_size) {
    const float* node_attr = (const float*)d_in[0];
    const float* edge_attr = (const float*)d_in[1];
    const int*   esrc      = (const int*)d_in[2];
    const int*   edst      = (const int*)d_in[3];
    const float* W_inner   = (const float*)d_in[4];
    const float* b_inner   = (const float*)d_in[5];
    const float* W_output  = (const float*)d_in[6];
    const float* b_output  = (const float*)d_in[7];
    float* out = (float*)d_out;

    int n = in_sizes[0] / NODE_F;   // 50000
    int m = in_sizes[2];            // 800000

    const int fp_smem = FP_SMEM_FLOATS * (int)sizeof(float);  // ~196.7 KB
    cudaFuncSetAttribute(k_fp, cudaFuncAttributeMaxDynamicSharedMemorySize, fp_smem);

    int nq = n * (DD / 4);          // n*64 float4 chunks per node-row pass
    k_zero<<<(nq + 255) / 256, 256>>>(out, n);
    k_init_attr<<<(nq + 255) / 256, 256>>>(node_attr, n);
    k_scatter_edge<<<(m * (EDGE_F / 4) + 255) / 256, 256>>>(edge_attr, edst, m);

    // depth 0 fingerprint
    k_fp<<<(n + FTM - 1) / FTM, 256, fp_smem>>>(W_output, b_output, out, n);

    for (int d = 1; d <= 3; ++d) {
        k_vinit<<<(nq + 255) / 256, 256>>>(n);
        k_scatter_attr<<<(m * (DD / 4) + 255) / 256, 256>>>(esrc, edst, m);
        k_inner<<<dim3((n + 63) / 64, DD / 64), 256>>>(
            W_inner + (size_t)(d - 1) * DD * DD, b_inner + (size_t)(d - 1) * DD, n);
        k_fp<<<(n + FTM - 1) / FTM, 256, fp_smem>>>(
            W_output + (size_t)d * DD * OUTF, b_output + (size_t)d * OUTF, out, n);
    }
}

// round 12
// speedup vs baseline: 1.1924x; 1.1891x over previous
#include <cuda_runtime.h>

// ---------------- problem constants ----------------
#define NODE_F 192
#define EDGE_F 64
#define DD     256          // inner dim
#define OUTF   2048
#define N_MAX  50000
#define M_MAX  800000

// ---------------- device scratch (no allocs allowed) ----------------
__device__ float g_attr[(size_t)N_MAX * DD];     // 51.2 MB
__device__ float g_v   [(size_t)N_MAX * DD];     // 51.2 MB
__device__ float g_eagg[(size_t)N_MAX * EDGE_F]; // 12.8 MB

// ---------------- f32x2 helpers (FFMA2) ----------------
__device__ __forceinline__ unsigned long long fma2(unsigned long long a,
                                                   unsigned long long b,
                                                   unsigned long long c) {
    unsigned long long d;
    asm("fma.rn.f32x2 %0, %1, %2, %3;" : "=l"(d) : "l"(a), "l"(b), "l"(c));
    return d;
}
__device__ __forceinline__ float2 u2f(unsigned long long u) {
    float2 f;
    asm("mov.b64 {%0, %1}, %2;" : "=f"(f.x), "=f"(f.y) : "l"(u));
    return f;
}
__device__ __forceinline__ void cp_async16(void* smem_dst, const void* gmem_src) {
    unsigned s = (unsigned)__cvta_generic_to_shared(smem_dst);
    asm volatile("cp.async.cg.shared.global [%0], [%1], 16;" :: "r"(s), "l"(gmem_src));
}

// ---------------- misc kernels ----------------
__global__ void k_zero(float* __restrict__ out, int n) {
    int idx = blockIdx.x * blockDim.x + threadIdx.x;
    if (idx < OUTF) out[idx] = 0.f;
    if (idx < n * EDGE_F) g_eagg[idx] = 0.f;
}

// attr = [node_attr | zeros]
__global__ void k_init_attr(const float* __restrict__ node, int n) {
    int idx = blockIdx.x * blockDim.x + threadIdx.x;
    if (idx >= n * (DD / 4)) return;
    int i = idx >> 6;
    int q = idx & 63;
    float4 v;
    if (q * 4 < NODE_F) v = *(const float4*)&node[(size_t)i * NODE_F + q * 4];
    else                v = make_float4(0.f, 0.f, 0.f, 0.f);
    *(float4*)&g_attr[(size_t)i * DD + q * 4] = v;
}

// g_eagg[dst] += edge_attr[e]  (attr-independent, once per launch)
__global__ void k_scatter_edge(const float* __restrict__ eattr,
                               const int* __restrict__ dst, int m) {
    int idx = blockIdx.x * blockDim.x + threadIdx.x;
    if (idx >= m * (EDGE_F / 4)) return;
    int e = idx >> 4;
    int q = idx & 15;
    float4 a = *(const float4*)&eattr[(size_t)e * EDGE_F + q * 4];
    int d2 = __ldg(&dst[e]);
    float* p = &g_eagg[(size_t)d2 * EDGE_F + q * 4];
    atomicAdd(p + 0, a.x); atomicAdd(p + 1, a.y);
    atomicAdd(p + 2, a.z); atomicAdd(p + 3, a.w);
}

// v = attr (+ eagg on last 64 features)
__global__ void k_vinit(int n) {
    int idx = blockIdx.x * blockDim.x + threadIdx.x;
    if (idx >= n * (DD / 4)) return;
    int i = idx >> 6;
    int q = idx & 63;
    float4 a = *(const float4*)&g_attr[(size_t)i * DD + q * 4];
    if (q >= NODE_F / 4) {
        float4 e = *(const float4*)&g_eagg[(size_t)i * EDGE_F + (q - NODE_F / 4) * 4];
        a.x += e.x; a.y += e.y; a.z += e.z; a.w += e.w;
    }
    *(float4*)&g_v[(size_t)i * DD + q * 4] = a;
}

// v[dst] += attr[src] over all edges
__global__ void k_scatter_attr(const int* __restrict__ src,
                               const int* __restrict__ dst, int m) {
    int idx = blockIdx.x * blockDim.x + threadIdx.x;
    int e = idx >> 6;
    int q = idx & 63;
    if (e >= m) return;
    int s  = __ldg(&src[e]);
    int d2 = __ldg(&dst[e]);
    float4 a = *(const float4*)&g_attr[(size_t)s * DD + q * 4];
    float* p = &g_v[(size_t)d2 * DD + q * 4];
    atomicAdd(p + 0, a.x); atomicAdd(p + 1, a.y);
    atomicAdd(p + 2, a.z); atomicAdd(p + 3, a.w);
}

// ---------------- inner GEMM: g_attr = g_v @ W + b  (N x 256 x 256) ----------------
__global__ void __launch_bounds__(256) k_inner(const float* __restrict__ W,
                                               const float* __restrict__ bias, int n) {
    __shared__ float sA[16][64];
    __shared__ float sB[16][64];
    int tid = threadIdx.x;
    int cx = tid & 15;
    int cy = tid >> 4;
    int row0 = blockIdx.x * 64;
    int col0 = blockIdx.y * 64;
    float acc[4][4] = {};

    int lr = tid >> 2;
    int lk = (tid & 3) << 2;
    int bk = tid >> 4;
    int bc = (tid & 15) << 2;

    for (int k0 = 0; k0 < DD; k0 += 16) {
        float4 a4 = make_float4(0.f, 0.f, 0.f, 0.f);
        int grow = row0 + lr;
        if (grow < n) a4 = *(const float4*)&g_v[(size_t)grow * DD + k0 + lk];
        float4 b4 = *(const float4*)&W[(size_t)(k0 + bk) * DD + col0 + bc];
        __syncthreads();
        sA[lk + 0][lr] = a4.x; sA[lk + 1][lr] = a4.y;
        sA[lk + 2][lr] = a4.z; sA[lk + 3][lr] = a4.w;
        *(float4*)&sB[bk][bc] = b4;
        __syncthreads();
#pragma unroll
        for (int kk = 0; kk < 16; ++kk) {
            float4 av = *(float4*)&sA[kk][cy * 4];
            float4 bv = *(float4*)&sB[kk][cx * 4];
            acc[0][0] += av.x * bv.x; acc[0][1] += av.x * bv.y; acc[0][2] += av.x * bv.z; acc[0][3] += av.x * bv.w;
            acc[1][0] += av.y * bv.x; acc[1][1] += av.y * bv.y; acc[1][2] += av.y * bv.z; acc[1][3] += av.y * bv.w;
            acc[2][0] += av.z * bv.x; acc[2][1] += av.z * bv.y; acc[2][2] += av.z * bv.z; acc[2][3] += av.z * bv.w;
            acc[3][0] += av.w * bv.x; acc[3][1] += av.w * bv.y; acc[3][2] += av.w * bv.z; acc[3][3] += av.w * bv.w;
        }
    }
    float4 bb = *(const float4*)&bias[col0 + cx * 4];
#pragma unroll
    for (int i = 0; i < 4; ++i) {
        int row = row0 + cy * 4 + i;
        if (row < n) {
            float4 o = make_float4(acc[i][0] + bb.x, acc[i][1] + bb.y,
                                   acc[i][2] + bb.z, acc[i][3] + bb.w);
            *(float4*)&g_attr[(size_t)row * DD + col0 + cx * 4] = o;
        }
    }
}

// ---------------- fused fingerprint: softmax(attr@W + b) summed over rows ----------------
// Block = 16 rows x ALL 2048 cols; logits stay entirely in registers.
// Two 128-thread row groups (8 rows each); per-thread tile 8 rows x 16 cols
// (acc = 64 x f32x2 = 128 regs). A is broadcast-LDS of dup pairs; W streamed
// via cp.async double buffer. No logit smem buffer at all.
#define FBK 8
#define A_STRIDE2 18                       // float2 stride per k (pad: kills 32-way store conflicts)
#define FP_SMEM_FLOATS (DD * A_STRIDE2 * 2 + 2 * FBK * OUTF + 128)

__global__ void __launch_bounds__(256, 1)
k_fp(const float* __restrict__ W,      // [DD][OUTF]
     const float* __restrict__ bias,   // [OUTF]
     float* __restrict__ fp_out, int n) {
    extern __shared__ float sm[];
    float* sAd  = sm;                          // DD * 18 float2 (dup pairs, padded)
    float* sB   = sAd + DD * A_STRIDE2 * 2;    // 2 x FBK x OUTF (double buffer)
    float* sRed = sB + 2 * FBK * OUTF;         // 128 floats reduction scratch

    int tid  = threadIdx.x;
    int row0 = blockIdx.x * 16;
    int g    = tid >> 7;        // row group (0: rows 0-7, 1: rows 8-15)
    int ct   = tid & 127;       // thread within group -> owns 4 col-chunks ct+j*128
    int lane = tid & 31;
    int wrp  = tid >> 5;        // 0..7 (warps 0-3 = group 0)

    // ---- load A rows as duplicated (a,a) pairs: sAd[k][row] = {a,a} ----
    for (int i = tid; i < 16 * DD; i += 256) {
        int mrow = i >> 8;            // i / 256
        int k    = i & 255;
        float v = 0.f;
        int r = row0 + mrow;
        if (r < n) v = g_attr[(size_t)r * DD + k];
        ((float2*)sAd)[k * A_STRIDE2 + mrow] = make_float2(v, v);
    }

    // ---- cp.async producer for W slices ----
    auto issue = [&](int buf, int k0) {
        float* dst = sB + buf * FBK * OUTF;
#pragma unroll
        for (int t = 0; t < (FBK * OUTF / 4) / 256; ++t) {   // 16 x 16B per thread
            int id   = tid + t * 256;
            int krow = id >> 9;          // / (OUTF/4)
            int ch   = id & 511;
            cp_async16(dst + krow * OUTF + ch * 4,
                       W + (size_t)(k0 + krow) * OUTF + ch * 4);
        }
        asm volatile("cp.async.commit_group;" ::: "memory");
    };
    issue(0, 0);
    issue(1, FBK);

    unsigned long long acc[8][8];
#pragma unroll
    for (int r = 0; r < 8; ++r)
#pragma unroll
        for (int c = 0; c < 8; ++c) acc[r][c] = 0ULL;

    // ---- main loop: 256 k-steps, double-buffered sB ----
    int p = 0;
    for (int k0 = 0; k0 < DD; k0 += FBK) {
        if (k0 == DD - FBK) asm volatile("cp.async.wait_group 0;" ::: "memory");
        else                asm volatile("cp.async.wait_group 1;" ::: "memory");
        __syncthreads();                    // sB[p] ready for everyone (also covers sAd 1st iter)
        const float* bb = sB + p * FBK * OUTF;
#pragma unroll
        for (int kk = 0; kk < FBK; ++kk) {
            ulonglong2 b2[4];
#pragma unroll
            for (int j = 0; j < 4; ++j)
                b2[j] = *(const ulonglong2*)&bb[kk * OUTF + (ct + j * 128) * 4];
            ulonglong2 a2[4];
            const ulonglong2* ap =
                (const ulonglong2*)sAd + (size_t)(k0 + kk) * (A_STRIDE2 / 2) + g * 4;
#pragma unroll
            for (int j = 0; j < 4; ++j) a2[j] = ap[j];   // warp-broadcast
#pragma unroll
            for (int ri = 0; ri < 4; ++ri) {
#pragma unroll
                for (int j = 0; j < 4; ++j) {
                    acc[2 * ri + 0][2 * j + 0] = fma2(a2[ri].x, b2[j].x, acc[2 * ri + 0][2 * j + 0]);
                    acc[2 * ri + 0][2 * j + 1] = fma2(a2[ri].x, b2[j].y, acc[2 * ri + 0][2 * j + 1]);
                    acc[2 * ri + 1][2 * j + 0] = fma2(a2[ri].y, b2[j].x, acc[2 * ri + 1][2 * j + 0]);
                    acc[2 * ri + 1][2 * j + 1] = fma2(a2[ri].y, b2[j].y, acc[2 * ri + 1][2 * j + 1]);
                }
            }
        }
        __syncthreads();                    // all warps done reading sB[p]
        if (k0 + 2 * FBK < DD) issue(p, k0 + 2 * FBK);
        p ^= 1;
    }

    // ---- epilogue: bias, softmax (registers + tiny reductions), column sums ----
    float4 bbias[4];
#pragma unroll
    for (int j = 0; j < 4; ++j)
        bbias[j] = *(const float4*)&bias[(ct + j * 128) * 4];

    float z[8][16];
#pragma unroll
    for (int r = 0; r < 8; ++r)
#pragma unroll
        for (int j = 0; j < 4; ++j) {
            float2 lo = u2f(acc[r][2 * j + 0]);
            float2 hi = u2f(acc[r][2 * j + 1]);
            z[r][4 * j + 0] = lo.x + bbias[j].x;
            z[r][4 * j + 1] = lo.y + bbias[j].y;
            z[r][4 * j + 2] = hi.x + bbias[j].z;
            z[r][4 * j + 3] = hi.y + bbias[j].w;
        }

    // per-row max across the 128-thread group
    float rmax[8];
#pragma unroll
    for (int r = 0; r < 8; ++r) {
        float m = z[r][0];
#pragma unroll
        for (int c = 1; c < 16; ++c) m = fmaxf(m, z[r][c]);
#pragma unroll
        for (int o = 16; o > 0; o >>= 1)
            m = fmaxf(m, __shfl_xor_sync(0xFFFFFFFFu, m, o));
        if (lane == 0) sRed[wrp * 8 + r] = m;
    }
    __syncthreads();
#pragma unroll
    for (int r = 0; r < 8; ++r) {
        float m = sRed[(g * 4 + 0) * 8 + r];
        m = fmaxf(m, sRed[(g * 4 + 1) * 8 + r]);
        m = fmaxf(m, sRed[(g * 4 + 2) * 8 + r]);
        m = fmaxf(m, sRed[(g * 4 + 3) * 8 + r]);
        rmax[r] = m;
    }

    // exp + row sums
    float rinv[8];
#pragma unroll
    for (int r = 0; r < 8; ++r) {
        float s = 0.f;
#pragma unroll
        for (int c = 0; c < 16; ++c) {
            float e = __expf(z[r][c] - rmax[r]);
            z[r][c] = e;
            s += e;
        }
#pragma unroll
        for (int o = 16; o > 0; o >>= 1)
            s += __shfl_xor_sync(0xFFFFFFFFu, s, o);
        if (lane == 0) sRed[64 + wrp * 8 + r] = s;
    }
    __syncthreads();
#pragma unroll
    for (int r = 0; r < 8; ++r) {
        float s = sRed[64 + (g * 4 + 0) * 8 + r] + sRed[64 + (g * 4 + 1) * 8 + r]
                + sRed[64 + (g * 4 + 2) * 8 + r] + sRed[64 + (g * 4 + 3) * 8 + r];
        rinv[r] = (row0 + g * 8 + r < n) ? (1.f / s) : 0.f;
    }

    // column sums over this group's 8 rows -> spread atomics
#pragma unroll
    for (int j = 0; j < 4; ++j)
#pragma unroll
        for (int cc = 0; cc < 4; ++cc) {
            float s = 0.f;
#pragma unroll
            for (int r = 0; r < 8; ++r) s += z[r][4 * j + cc] * rinv[r];
            atomicAdd(&fp_out[(ct + j * 128) * 4 + cc], s);
        }
}

// ---------------- launch ----------------
extern "C" void kernel_launch(void* const* d_in, const int* in_sizes, int n_in,
                              void* d_out, int out_size) {
    const float* node_attr = (const float*)d_in[0];
    const float* edge_attr = (const float*)d_in[1];
    const int*   esrc      = (const int*)d_in[2];
    const int*   edst      = (const int*)d_in[3];
    const float* W_inner   = (const float*)d_in[4];
    const float* b_inner   = (const float*)d_in[5];
    const float* W_output  = (const float*)d_in[6];
    const float* b_output  = (const float*)d_in[7];
    float* out = (float*)d_out;

    int n = in_sizes[0] / NODE_F;   // 50000
    int m = in_sizes[2];            // 800000

    const int fp_smem = FP_SMEM_FLOATS * (int)sizeof(float);  // ~168 KB
    cudaFuncSetAttribute(k_fp, cudaFuncAttributeMaxDynamicSharedMemorySize, fp_smem);

    int nq = n * (DD / 4);
    k_zero<<<(nq + 255) / 256, 256>>>(out, n);
    k_init_attr<<<(nq + 255) / 256, 256>>>(node_attr, n);
    k_scatter_edge<<<(m * (EDGE_F / 4) + 255) / 256, 256>>>(edge_attr, edst, m);

    // depth 0 fingerprint
    k_fp<<<(n + 15) / 16, 256, fp_smem>>>(W_output, b_output, out, n);

    for (int d = 1; d <= 3; ++d) {
        k_vinit<<<(nq + 255) / 256, 256>>>(n);
        k_scatter_attr<<<(m * (DD / 4) + 255) / 256, 256>>>(esrc, edst, m);
        k_inner<<<dim3((n + 63) / 64, DD / 64), 256>>>(
            W_inner + (size_t)(d - 1) * DD * DD, b_inner + (size_t)(d - 1) * DD, n);
        k_fp<<<(n + 15) / 16, 256, fp_smem>>>(
            W_output + (size_t)d * DD * OUTF, b_output + (size_t)d * OUTF, out, n);
    }
}